// round 2
// baseline (speedup 1.0000x reference)
#include <cuda_runtime.h>
#include <cuda_bf16.h>
#include <cstdint>

// ============================================================================
// MotherCubeConv: y[n] = concat(x[n], x[nbr0..3(n)]) @ W^T + b
//   N=200000, F_in=128, fan_in=640, F_out=128.
// Portable tensor path (compute_103 target => no tcgen05): warp-level
// mma.sync.m16n8k16 bf16 with fp32 accum, hi/lo split (3 terms) for accuracy.
// ============================================================================

#define NSLOT 5

// ---- scratch (__device__ globals; no allocation allowed) -------------------
__device__ uint4 g_Whi[NSLOT * 2048];   // 5 x [128 out x 128 k] bf16, swizzled
__device__ uint4 g_Wlo[NSLOT * 2048];
__device__ int   g_is64;                // neighbors dtype flag

// ---- helpers ----------------------------------------------------------------
__device__ __forceinline__ uint32_t smem_u32(const void* p) {
    uint32_t a;
    asm("{ .reg .u64 t; cvta.to.shared.u64 t, %1; cvt.u32.u64 %0, t; }"
        : "=r"(a) : "l"(p));
    return a;
}

__device__ __forceinline__ void ldsm_x4(uint32_t* r, uint32_t addr) {
    asm volatile("ldmatrix.sync.aligned.m8n8.x4.shared.b16 {%0,%1,%2,%3}, [%4];"
                 : "=r"(r[0]), "=r"(r[1]), "=r"(r[2]), "=r"(r[3]) : "r"(addr));
}
__device__ __forceinline__ void ldsm_x2(uint32_t* r, uint32_t addr) {
    asm volatile("ldmatrix.sync.aligned.m8n8.x2.shared.b16 {%0,%1}, [%2];"
                 : "=r"(r[0]), "=r"(r[1]) : "r"(addr));
}

__device__ __forceinline__ void mma16816(float* d, const uint32_t* a,
                                         const uint32_t* b) {
    asm volatile(
        "mma.sync.aligned.m16n8k16.row.col.f32.bf16.bf16.f32 "
        "{%0,%1,%2,%3}, {%4,%5,%6,%7}, {%8,%9}, {%0,%1,%2,%3};"
        : "+f"(d[0]), "+f"(d[1]), "+f"(d[2]), "+f"(d[3])
        : "r"(a[0]), "r"(a[1]), "r"(a[2]), "r"(a[3]), "r"(b[0]), "r"(b[1]));
}

// Swizzled byte offset inside one [128 rows x 128 bf16] tile (32KB).
// Row stride 256B (16 groups of 16B); group XOR-swizzled by row&7 so
// ldmatrix (8 rows, same group) is bank-conflict free.
__device__ __host__ __forceinline__ uint32_t tile_off(int row, int k) {
    uint32_t g = (uint32_t)(k >> 3);
    return (uint32_t)row * 256u + (((g ^ (uint32_t)(row & 7)) << 4)) +
           (uint32_t)(k & 7) * 2u;
}

// ---- prologue: split W into bf16 hi/lo, pre-swizzled per neighbor slot -----
__global__ void prep_w_kernel(const float* __restrict__ W) {
    int t = blockIdx.x * blockDim.x + threadIdx.x;   // over 5*128*64 col-pairs
    if (t >= NSLOT * 128 * 64) return;
    int cp = t & 63;            // col pair index (k/2)
    int f  = (t >> 6) & 127;    // output feature (tile row)
    int j  = t >> 13;           // neighbor slot
    int k  = cp * 2;
    float w0 = W[f * 640 + j * 128 + k];
    float w1 = W[f * 640 + j * 128 + k + 1];
    __nv_bfloat16 h0 = __float2bfloat16_rn(w0);
    __nv_bfloat16 h1 = __float2bfloat16_rn(w1);
    __nv_bfloat16 l0 = __float2bfloat16_rn(w0 - __bfloat162float(h0));
    __nv_bfloat16 l1 = __float2bfloat16_rn(w1 - __bfloat162float(h1));
    uint32_t hiw = (uint32_t)__bfloat16_as_ushort(h0) |
                   ((uint32_t)__bfloat16_as_ushort(h1) << 16);
    uint32_t low = (uint32_t)__bfloat16_as_ushort(l0) |
                   ((uint32_t)__bfloat16_as_ushort(l1) << 16);
    uint32_t off = tile_off(f, k);
    *(uint32_t*)((char*)g_Whi + (size_t)j * 32768 + off) = hiw;
    *(uint32_t*)((char*)g_Wlo + (size_t)j * 32768 + off) = low;
}

// ---- prologue: detect neighbors dtype (int64 vs silently-downcast int32) ---
__global__ void detect_kernel(const int* __restrict__ w) {
    if (threadIdx.x == 0 && blockIdx.x == 0) {
        int all0 = 1;
        for (int i = 0; i < 64; i++)
            if (w[2 * i + 1] != 0) { all0 = 0; break; }
        g_is64 = all0;
    }
}

// ---- SMEM layout --------------------------------------------------------------
static constexpr uint32_t OFF_BIAS = 0;       // 512B
static constexpr uint32_t OFF_AHI  = 1024;    // 32KB
static constexpr uint32_t OFF_ALO  = 33792;   // 32KB
static constexpr uint32_t OFF_WHI  = 66560;   // 32KB
static constexpr uint32_t OFF_WLO  = 99328;   // 32KB
static constexpr uint32_t SMEM_BYTES = 132096;

__global__ void __launch_bounds__(256, 1)
mcconv_kernel(const float* __restrict__ x, const void* __restrict__ nbr_raw,
              const float* __restrict__ bias_g, float* __restrict__ out, int N) {
    extern __shared__ char smem[];
    const uint32_t sb = smem_u32(smem);
    const int tid = threadIdx.x;
    const int wid = tid >> 5;
    const int lid = tid & 31;

    if (tid < 128) ((float*)(smem + OFF_BIAS))[tid] = bias_g[tid];

    const int row0  = blockIdx.x * 128;
    const int grow  = row0 + (tid >> 1);     // gather: row this thread fills
    const int half  = tid & 1;               // which 64-col half of the row
    const bool gvalid = grow < N;
    const int is64 = g_is64;
    const long long* nbr64 = (const long long*)nbr_raw;
    const int*       nbr32 = (const int*)nbr_raw;

    // warp tiling: 2 (M) x 4 (N); warp tile = 64 rows x 32 cols
    const int wm = wid >> 2;
    const int wn = wid & 3;

    float acc[4][4][4];   // [mt][nt][reg]
    #pragma unroll
    for (int mt = 0; mt < 4; ++mt)
        #pragma unroll
        for (int nt = 0; nt < 4; ++nt)
            #pragma unroll
            for (int q = 0; q < 4; ++q) acc[mt][nt][q] = 0.0f;

    // precomputed per-lane ldmatrix coordinates
    const int a_row  = (lid & 15);           // + wm*64 + mt*16
    const int a_gsel = (lid >> 4);           // + kc*2
    const int b_row  = (lid & 7);            // + wn*32 + nt*8  (lanes 0-15 used)
    const int b_gsel = ((lid >> 3) & 1);     // + kc*2

    for (int j = 0; j < NSLOT; ++j) {
        // --- stage W_j hi/lo (pre-swizzled, flat 32KB copies) ---
        {
            const uint4* wh = g_Whi + (size_t)j * 2048;
            const uint4* wl = g_Wlo + (size_t)j * 2048;
            uint4* swh = (uint4*)(smem + OFF_WHI);
            uint4* swl = (uint4*)(smem + OFF_WLO);
            #pragma unroll
            for (int i = tid; i < 2048; i += 256) {
                swh[i] = wh[i];
                swl[i] = wl[i];
            }
        }
        // --- gather + fp32 -> bf16 hi/lo split into swizzled SMEM ---
        {
            long long g = gvalid ? (long long)grow : 0;
            if (j > 0 && gvalid) {
                g = is64 ? nbr64[(size_t)grow * 4 + (j - 1)]
                         : (long long)nbr32[(size_t)grow * 4 + (j - 1)];
            }
            const int r = tid >> 1;
            const float4* src = (const float4*)(x + (size_t)g * 128 + half * 64);
            #pragma unroll
            for (int i = 0; i < 8; ++i) {
                float4 fa = src[2 * i];
                float4 fb = src[2 * i + 1];
                float v[8] = {fa.x, fa.y, fa.z, fa.w, fb.x, fb.y, fb.z, fb.w};
                uint32_t hw[4], lw[4];
                #pragma unroll
                for (int q = 0; q < 4; ++q) {
                    float a = v[2 * q], b = v[2 * q + 1];
                    __nv_bfloat16 ha = __float2bfloat16_rn(a);
                    __nv_bfloat16 hb = __float2bfloat16_rn(b);
                    __nv_bfloat16 la = __float2bfloat16_rn(a - __bfloat162float(ha));
                    __nv_bfloat16 lb = __float2bfloat16_rn(b - __bfloat162float(hb));
                    hw[q] = (uint32_t)__bfloat16_as_ushort(ha) |
                            ((uint32_t)__bfloat16_as_ushort(hb) << 16);
                    lw[q] = (uint32_t)__bfloat16_as_ushort(la) |
                            ((uint32_t)__bfloat16_as_ushort(lb) << 16);
                }
                uint32_t off = tile_off(r, half * 64 + i * 8);
                *(uint4*)(smem + OFF_AHI + off) = make_uint4(hw[0], hw[1], hw[2], hw[3]);
                *(uint4*)(smem + OFF_ALO + off) = make_uint4(lw[0], lw[1], lw[2], lw[3]);
            }
        }
        __syncthreads();

        // --- MMA phase: K=128 in 8 chunks of 16 ---
        #pragma unroll
        for (int kc = 0; kc < 8; ++kc) {
            // B fragments for this k-chunk: 4 n-tiles, hi + lo
            uint32_t bh[4][2], bl[4][2];
            {
                const int gB = kc * 2 + b_gsel;
                #pragma unroll
                for (int nt = 0; nt < 4; ++nt) {
                    const int nr = wn * 32 + nt * 8 + b_row;
                    const uint32_t off =
                        (uint32_t)nr * 256u +
                        (((uint32_t)(gB ^ (nr & 7))) << 4);
                    ldsm_x2(bh[nt], sb + OFF_WHI + off);
                    ldsm_x2(bl[nt], sb + OFF_WLO + off);
                }
            }
            const int gA = kc * 2 + a_gsel;
            #pragma unroll
            for (int mt = 0; mt < 4; ++mt) {
                const int ar = wm * 64 + mt * 16 + a_row;
                const uint32_t off =
                    (uint32_t)ar * 256u + (((uint32_t)(gA ^ (ar & 7))) << 4);
                uint32_t ah[4], al[4];
                ldsm_x4(ah, sb + OFF_AHI + off);
                ldsm_x4(al, sb + OFF_ALO + off);
                #pragma unroll
                for (int nt = 0; nt < 4; ++nt) {
                    mma16816(acc[mt][nt], ah, bh[nt]);
                    mma16816(acc[mt][nt], al, bh[nt]);
                    mma16816(acc[mt][nt], ah, bl[nt]);
                }
            }
        }
        __syncthreads();   // MMA reads done before next slot overwrites SMEM
    }

    // --- epilogue: d-frag lane mapping: (r=lid>>2, c=(lid&3)*2) ---
    {
        const float* bs = (const float*)(smem + OFF_BIAS);
        const int rl = lid >> 2;
        const int cl = (lid & 3) * 2;
        #pragma unroll
        for (int mt = 0; mt < 4; ++mt) {
            const int r_base = row0 + wm * 64 + mt * 16 + rl;
            #pragma unroll
            for (int nt = 0; nt < 4; ++nt) {
                const int col = wn * 32 + nt * 8 + cl;
                const float b0 = bs[col], b1 = bs[col + 1];
                if (r_base < N) {
                    float2 v = make_float2(acc[mt][nt][0] + b0,
                                           acc[mt][nt][1] + b1);
                    *(float2*)(out + (size_t)r_base * 128 + col) = v;
                }
                if (r_base + 8 < N) {
                    float2 v = make_float2(acc[mt][nt][2] + b0,
                                           acc[mt][nt][3] + b1);
                    *(float2*)(out + (size_t)(r_base + 8) * 128 + col) = v;
                }
            }
        }
    }
}

// ---- launch ------------------------------------------------------------------
extern "C" void kernel_launch(void* const* d_in, const int* in_sizes, int n_in,
                              void* d_out, int out_size) {
    const float* x   = (const float*)d_in[0];
    const void*  nbr = d_in[1];
    const float* W   = (const float*)d_in[2];
    const float* b   = (const float*)d_in[3];
    float* out = (float*)d_out;
    const int N = in_sizes[0] / 128;
    const int tiles = (N + 127) / 128;

    cudaFuncSetAttribute(mcconv_kernel,
                         cudaFuncAttributeMaxDynamicSharedMemorySize, SMEM_BYTES);

    prep_w_kernel<<<(NSLOT * 128 * 64 + 255) / 256, 256>>>(W);
    detect_kernel<<<1, 32>>>((const int*)nbr);
    mcconv_kernel<<<tiles, 256, SMEM_BYTES>>>(x, nbr, b, out, N);
}

// round 3
// speedup vs baseline: 1.4638x; 1.4638x over previous
#include <cuda_runtime.h>
#include <cuda_fp16.h>
#include <cstdint>

// ============================================================================
// MotherCubeConv: y[n] = concat(x[n], x[nbr0..3(n)]) @ W^T + b
//   N=200000, F_in=128, fan_in=640, F_out=128.
// Single-term fp16 mma.sync (legacy HMMA path; tcgen05 unavailable at
// compute_103). All 5 W slots resident in SMEM (160KB); double-buffered
// gathered A tile with LDG-before-MMA / convert-after-MMA pipelining.
// ============================================================================

#define NSLOT 5

// ---- scratch (__device__ globals; no allocation allowed) -------------------
__device__ uint4 g_Wh[NSLOT * 2048];    // 5 x [128 out x 128 k] fp16, swizzled
__device__ int   g_is64;                // neighbors dtype flag

// ---- helpers ----------------------------------------------------------------
__device__ __forceinline__ uint32_t smem_u32(const void* p) {
    uint32_t a;
    asm("{ .reg .u64 t; cvta.to.shared.u64 t, %1; cvt.u32.u64 %0, t; }"
        : "=r"(a) : "l"(p));
    return a;
}

__device__ __forceinline__ void ldsm_x4(uint32_t* r, uint32_t addr) {
    asm volatile("ldmatrix.sync.aligned.m8n8.x4.shared.b16 {%0,%1,%2,%3}, [%4];"
                 : "=r"(r[0]), "=r"(r[1]), "=r"(r[2]), "=r"(r[3]) : "r"(addr));
}
__device__ __forceinline__ void ldsm_x2(uint32_t* r, uint32_t addr) {
    asm volatile("ldmatrix.sync.aligned.m8n8.x2.shared.b16 {%0,%1}, [%2];"
                 : "=r"(r[0]), "=r"(r[1]) : "r"(addr));
}

__device__ __forceinline__ void mma16816(float* d, const uint32_t* a,
                                         const uint32_t* b) {
    asm volatile(
        "mma.sync.aligned.m16n8k16.row.col.f32.f16.f16.f32 "
        "{%0,%1,%2,%3}, {%4,%5,%6,%7}, {%8,%9}, {%0,%1,%2,%3};"
        : "+f"(d[0]), "+f"(d[1]), "+f"(d[2]), "+f"(d[3])
        : "r"(a[0]), "r"(a[1]), "r"(a[2]), "r"(a[3]), "r"(b[0]), "r"(b[1]));
}

#define CP_ASYNC16(dst, src) \
    asm volatile("cp.async.cg.shared.global [%0], [%1], 16;" \
                 :: "r"(dst), "l"(src) : "memory")

// Swizzled byte offset inside one [128 rows x 128 fp16] tile (32KB).
// Row stride 256B (16 groups of 16B); group XOR-swizzled by row&7.
__device__ __host__ __forceinline__ uint32_t tile_off(int row, int k) {
    uint32_t g = (uint32_t)(k >> 3);
    return (uint32_t)row * 256u + (((g ^ (uint32_t)(row & 7)) << 4)) +
           (uint32_t)(k & 7) * 2u;
}

// ---- prologue: W -> fp16, pre-swizzled per neighbor slot --------------------
__global__ void prep_w_kernel(const float* __restrict__ W) {
    int t = blockIdx.x * blockDim.x + threadIdx.x;   // over 5*128*64 col-pairs
    if (t >= NSLOT * 128 * 64) return;
    int cp = t & 63;            // col pair index (k/2)
    int f  = (t >> 6) & 127;    // output feature (tile row)
    int j  = t >> 13;           // neighbor slot
    int k  = cp * 2;
    __half2 h = __floats2half2_rn(W[f * 640 + j * 128 + k],
                                  W[f * 640 + j * 128 + k + 1]);
    uint32_t off = tile_off(f, k);
    *(uint32_t*)((char*)g_Wh + (size_t)j * 32768 + off) = *(uint32_t*)&h;
}

// ---- prologue: detect neighbors dtype (int64 vs silently-downcast int32) ---
__global__ void detect_kernel(const int* __restrict__ w) {
    if (threadIdx.x == 0 && blockIdx.x == 0) {
        int all0 = 1;
        for (int i = 0; i < 64; i++)
            if (w[2 * i + 1] != 0) { all0 = 0; break; }
        g_is64 = all0;
    }
}

// ---- SMEM layout --------------------------------------------------------------
static constexpr uint32_t OFF_BIAS = 0;        // 512B
static constexpr uint32_t OFF_W    = 1024;     // 5 x 32KB = 160KB
static constexpr uint32_t OFF_A    = 164864;   // 2 x 32KB
static constexpr uint32_t SMEM_BYTES = 230400;

__device__ __forceinline__ void cvt_store(char* smem, uint32_t abase, int r,
                                          int half, const float4* v) {
    #pragma unroll
    for (int i = 0; i < 8; ++i) {
        float4 fa = v[2 * i];
        float4 fb = v[2 * i + 1];
        __half2 h0 = __floats2half2_rn(fa.x, fa.y);
        __half2 h1 = __floats2half2_rn(fa.z, fa.w);
        __half2 h2 = __floats2half2_rn(fb.x, fb.y);
        __half2 h3 = __floats2half2_rn(fb.z, fb.w);
        uint4 u;
        u.x = *(uint32_t*)&h0;
        u.y = *(uint32_t*)&h1;
        u.z = *(uint32_t*)&h2;
        u.w = *(uint32_t*)&h3;
        *(uint4*)(smem + abase + tile_off(r, half * 64 + i * 8)) = u;
    }
}

__global__ void __launch_bounds__(256, 1)
mcconv_kernel(const float* __restrict__ x, const void* __restrict__ nbr_raw,
              const float* __restrict__ bias_g, float* __restrict__ out, int N) {
    extern __shared__ char smem[];
    const uint32_t sb = smem_u32(smem);
    const int tid = threadIdx.x;
    const int wid = tid >> 5;
    const int lid = tid & 31;

    if (tid < 128) ((float*)(smem + OFF_BIAS))[tid] = bias_g[tid];

    // ---- cp.async: stage all 5 W slots (160KB), one commit group per slot ---
    #pragma unroll
    for (int j = 0; j < NSLOT; ++j) {
        const char* src = (const char*)g_Wh + (size_t)j * 32768;
        const uint32_t dst = sb + OFF_W + (uint32_t)j * 32768;
        #pragma unroll
        for (int w = 0; w < 8; ++w) {
            const uint32_t e = (uint32_t)(tid + w * 256) * 16u;
            CP_ASYNC16(dst + e, src + e);
        }
        asm volatile("cp.async.commit_group;" ::: "memory");
    }

    // ---- neighbor indices (once) ---------------------------------------------
    const int row0 = blockIdx.x * 128;
    const int r    = tid >> 1;
    const int half = tid & 1;
    const int grow = row0 + r;
    const bool gvalid = grow < N;
    int idxs[NSLOT];
    idxs[0] = gvalid ? grow : 0;
    if (g_is64) {
        const long long* p = (const long long*)nbr_raw + (size_t)(gvalid ? grow : 0) * 4;
        #pragma unroll
        for (int k = 0; k < 4; ++k) idxs[k + 1] = gvalid ? (int)p[k] : 0;
    } else {
        const int* p = (const int*)nbr_raw + (size_t)(gvalid ? grow : 0) * 4;
        #pragma unroll
        for (int k = 0; k < 4; ++k) idxs[k + 1] = gvalid ? p[k] : 0;
    }

    // ---- prologue: gather + convert slot 0 into A buffer 0 -------------------
    {
        const float4* src = (const float4*)(x + (size_t)idxs[0] * 128 + half * 64);
        float4 v[16];
        #pragma unroll
        for (int i = 0; i < 16; ++i) v[i] = src[i];
        cvt_store(smem, OFF_A, r, half, v);
    }

    // warp tiling: 2 (M) x 4 (N); warp tile = 64 rows x 32 cols
    const int wm = wid >> 2;
    const int wn = wid & 3;

    float acc[4][4][4];
    #pragma unroll
    for (int mt = 0; mt < 4; ++mt)
        #pragma unroll
        for (int nt = 0; nt < 4; ++nt)
            #pragma unroll
            for (int q = 0; q < 4; ++q) acc[mt][nt][q] = 0.0f;

    const int a_row  = (lid & 15);
    const int a_gsel = (lid >> 4);
    const int b_row  = (lid & 7);
    const int b_gsel = ((lid >> 3) & 1);

    int pbuf = 0;
    #pragma unroll
    for (int j = 0; j < NSLOT; ++j) {
        // prefetch next slot's gather (LDGs issue now, consumed after MMA)
        float4 v[16];
        if (j < NSLOT - 1) {
            const float4* src =
                (const float4*)(x + (size_t)idxs[j + 1] * 128 + half * 64);
            #pragma unroll
            for (int i = 0; i < 16; ++i) v[i] = src[i];
        }

        // W_j must have landed (groups committed in slot order)
        if      (j == 0) asm volatile("cp.async.wait_group 4;" ::: "memory");
        else if (j == 1) asm volatile("cp.async.wait_group 3;" ::: "memory");
        else if (j == 2) asm volatile("cp.async.wait_group 2;" ::: "memory");
        else if (j == 3) asm volatile("cp.async.wait_group 1;" ::: "memory");
        else             asm volatile("cp.async.wait_group 0;" ::: "memory");
        __syncthreads();   // W_j + A_j (STS from previous iter) visible

        // ---- MMA over slot j: K=128 in 8 chunks of 16 -------------------------
        const uint32_t wbase = sb + OFF_W + (uint32_t)j * 32768;
        const uint32_t abase = sb + OFF_A + (uint32_t)pbuf * 32768;
        #pragma unroll
        for (int kc = 0; kc < 8; ++kc) {
            uint32_t bh[4][2];
            const int gB = kc * 2 + b_gsel;
            #pragma unroll
            for (int nt = 0; nt < 4; ++nt) {
                const int nr = wn * 32 + nt * 8 + b_row;
                const uint32_t off =
                    (uint32_t)nr * 256u + (((uint32_t)(gB ^ (nr & 7))) << 4);
                ldsm_x2(bh[nt], wbase + off);
            }
            const int gA = kc * 2 + a_gsel;
            #pragma unroll
            for (int mt = 0; mt < 4; ++mt) {
                const int ar = wm * 64 + mt * 16 + a_row;
                const uint32_t off =
                    (uint32_t)ar * 256u + (((uint32_t)(gA ^ (ar & 7))) << 4);
                uint32_t ah[4];
                ldsm_x4(ah, abase + off);
                #pragma unroll
                for (int nt = 0; nt < 4; ++nt)
                    mma16816(acc[mt][nt], ah, bh[nt]);
            }
        }

        // convert prefetched gather into the other buffer
        if (j < NSLOT - 1) {
            cvt_store(smem, OFF_A + (uint32_t)(pbuf ^ 1) * 32768, r, half, v);
            pbuf ^= 1;
        }
    }

    // ---- epilogue: d-frag lane mapping (r=lid>>2, c=(lid&3)*2) ----------------
    {
        const float* bs = (const float*)(smem + OFF_BIAS);
        const int rl = lid >> 2;
        const int cl = (lid & 3) * 2;
        #pragma unroll
        for (int mt = 0; mt < 4; ++mt) {
            const int r_base = row0 + wm * 64 + mt * 16 + rl;
            #pragma unroll
            for (int nt = 0; nt < 4; ++nt) {
                const int col = wn * 32 + nt * 8 + cl;
                const float b0 = bs[col], b1 = bs[col + 1];
                if (r_base < N) {
                    float2 vv = make_float2(acc[mt][nt][0] + b0,
                                            acc[mt][nt][1] + b1);
                    *(float2*)(out + (size_t)r_base * 128 + col) = vv;
                }
                if (r_base + 8 < N) {
                    float2 vv = make_float2(acc[mt][nt][2] + b0,
                                            acc[mt][nt][3] + b1);
                    *(float2*)(out + (size_t)(r_base + 8) * 128 + col) = vv;
                }
            }
        }
    }
}

// ---- launch ------------------------------------------------------------------
extern "C" void kernel_launch(void* const* d_in, const int* in_sizes, int n_in,
                              void* d_out, int out_size) {
    const float* x   = (const float*)d_in[0];
    const void*  nbr = d_in[1];
    const float* W   = (const float*)d_in[2];
    const float* b   = (const float*)d_in[3];
    float* out = (float*)d_out;
    const int N = in_sizes[0] / 128;
    const int tiles = (N + 127) / 128;

    cudaFuncSetAttribute(mcconv_kernel,
                         cudaFuncAttributeMaxDynamicSharedMemorySize, SMEM_BYTES);

    prep_w_kernel<<<(NSLOT * 128 * 64 + 255) / 256, 256>>>(W);
    detect_kernel<<<1, 32>>>((const int*)nbr);
    mcconv_kernel<<<tiles, 256, SMEM_BYTES>>>(x, nbr, b, out, N);
}

// round 4
// speedup vs baseline: 2.9172x; 1.9929x over previous
#include <cuda_runtime.h>
#include <cuda_fp16.h>
#include <cstdint>

// ============================================================================
// MotherCubeConv: y[n] = concat(x[n], x[nbr0..3(n)]) @ W^T + b
//   N=200000, F_in=128, fan_in=640, F_out=128.
// fp16 mma.sync path. Round 4: global fp16 image of x built once per launch;
// gathered A tiles staged via cp.async directly into swizzled SMEM (no regs,
// no in-loop conversion); W fully SMEM-resident; 512 threads, 4x4 warp grid.
// ============================================================================

#define NSLOT 5
#define MAX_ROWS 200704

// ---- scratch (__device__ globals; no allocation allowed) -------------------
__device__ uint4 g_Wh[NSLOT * 2048];            // 5 x [128x128] fp16, swizzled
__device__ uint4 g_x16[(size_t)MAX_ROWS * 16];  // fp16 image of x (51.4MB)
__device__ int   g_is64;

// ---- helpers ----------------------------------------------------------------
__device__ __forceinline__ uint32_t smem_u32(const void* p) {
    uint32_t a;
    asm("{ .reg .u64 t; cvta.to.shared.u64 t, %1; cvt.u32.u64 %0, t; }"
        : "=r"(a) : "l"(p));
    return a;
}

__device__ __forceinline__ void ldsm_x4(uint32_t* r, uint32_t addr) {
    asm volatile("ldmatrix.sync.aligned.m8n8.x4.shared.b16 {%0,%1,%2,%3}, [%4];"
                 : "=r"(r[0]), "=r"(r[1]), "=r"(r[2]), "=r"(r[3]) : "r"(addr));
}
__device__ __forceinline__ void ldsm_x2(uint32_t* r, uint32_t addr) {
    asm volatile("ldmatrix.sync.aligned.m8n8.x2.shared.b16 {%0,%1}, [%2];"
                 : "=r"(r[0]), "=r"(r[1]) : "r"(addr));
}

__device__ __forceinline__ void mma16816(float* d, const uint32_t* a,
                                         const uint32_t* b) {
    asm volatile(
        "mma.sync.aligned.m16n8k16.row.col.f32.f16.f16.f32 "
        "{%0,%1,%2,%3}, {%4,%5,%6,%7}, {%8,%9}, {%0,%1,%2,%3};"
        : "+f"(d[0]), "+f"(d[1]), "+f"(d[2]), "+f"(d[3])
        : "r"(a[0]), "r"(a[1]), "r"(a[2]), "r"(a[3]), "r"(b[0]), "r"(b[1]));
}

#define CP_ASYNC16(dst, src) \
    asm volatile("cp.async.cg.shared.global [%0], [%1], 16;" \
                 :: "r"(dst), "l"(src) : "memory")
#define CP_COMMIT() asm volatile("cp.async.commit_group;" ::: "memory")

// Swizzled byte offset inside one [128 rows x 128 fp16] tile (32KB).
__device__ __host__ __forceinline__ uint32_t tile_off(int row, int k) {
    uint32_t g = (uint32_t)(k >> 3);
    return (uint32_t)row * 256u + (((g ^ (uint32_t)(row & 7)) << 4)) +
           (uint32_t)(k & 7) * 2u;
}

// ---- prologue: W -> fp16, pre-swizzled per neighbor slot --------------------
__global__ void prep_w_kernel(const float* __restrict__ W) {
    int t = blockIdx.x * blockDim.x + threadIdx.x;
    if (t >= NSLOT * 128 * 64) return;
    int cp = t & 63;
    int f  = (t >> 6) & 127;
    int j  = t >> 13;
    int k  = cp * 2;
    __half2 h = __floats2half2_rn(W[f * 640 + j * 128 + k],
                                  W[f * 640 + j * 128 + k + 1]);
    *(uint32_t*)((char*)g_Wh + (size_t)j * 32768 + tile_off(f, k)) =
        *(uint32_t*)&h;
}

// ---- prologue: x (fp32) -> g_x16 (fp16), 8 elems per thread -----------------
__global__ void cvt_x_kernel(const float* __restrict__ x, int ngroups) {
    int t = blockIdx.x * blockDim.x + threadIdx.x;
    if (t >= ngroups) return;
    const float4* s = (const float4*)x + (size_t)t * 2;
    float4 a = s[0], b = s[1];
    __half2 h0 = __floats2half2_rn(a.x, a.y);
    __half2 h1 = __floats2half2_rn(a.z, a.w);
    __half2 h2 = __floats2half2_rn(b.x, b.y);
    __half2 h3 = __floats2half2_rn(b.z, b.w);
    uint4 u;
    u.x = *(uint32_t*)&h0; u.y = *(uint32_t*)&h1;
    u.z = *(uint32_t*)&h2; u.w = *(uint32_t*)&h3;
    g_x16[t] = u;
}

// ---- prologue: detect neighbors dtype ---------------------------------------
__global__ void detect_kernel(const int* __restrict__ w) {
    if (threadIdx.x == 0 && blockIdx.x == 0) {
        int all0 = 1;
        for (int i = 0; i < 64; i++)
            if (w[2 * i + 1] != 0) { all0 = 0; break; }
        g_is64 = all0;
    }
}

// ---- SMEM layout --------------------------------------------------------------
static constexpr uint32_t OFF_BIAS = 0;        // 512B
static constexpr uint32_t OFF_W    = 1024;     // 5 x 32KB
static constexpr uint32_t OFF_A    = 164864;   // 2 x 32KB
static constexpr uint32_t SMEM_BYTES = 230400;

__global__ void __launch_bounds__(512, 1)
mcconv_kernel(const void* __restrict__ nbr_raw,
              const float* __restrict__ bias_g, float* __restrict__ out, int N) {
    extern __shared__ char smem[];
    const uint32_t sb = smem_u32(smem);
    const int tid = threadIdx.x;
    const int wid = tid >> 5;
    const int lid = tid & 31;

    if (tid < 128) ((float*)(smem + OFF_BIAS))[tid] = bias_g[tid];

    // ---- stage all W (160KB) in one commit group ------------------------------
    {
        const char* src = (const char*)g_Wh;
        const uint32_t dst = sb + OFF_W;
        #pragma unroll
        for (int w = 0; w < 20; ++w) {
            const uint32_t e = (uint32_t)(tid + w * 512) * 16u;
            CP_ASYNC16(dst + e, src + e);
        }
        CP_COMMIT();   // group: W
    }

    // ---- per-thread gather assignment: 4 threads per row ----------------------
    const int row0 = blockIdx.x * 128;
    const int r    = tid >> 2;            // tile row 0..127
    const int c0   = (tid & 3) * 4;       // first of 4 16B-chunks (of 16)
    const int grow = row0 + r;
    const bool gvalid = grow < N;
    int idxs[NSLOT];
    idxs[0] = gvalid ? grow : 0;
    if (g_is64) {
        const long long* p = (const long long*)nbr_raw + (size_t)idxs[0] * 4;
        #pragma unroll
        for (int k = 0; k < 4; ++k) idxs[k + 1] = gvalid ? (int)p[k] : 0;
    } else {
        const int* p = (const int*)nbr_raw + (size_t)idxs[0] * 4;
        #pragma unroll
        for (int k = 0; k < 4; ++k) idxs[k + 1] = gvalid ? p[k] : 0;
    }

    // stage A slot j into buffer `buf` (cp.async, swizzled dst)
    auto stage_A = [&](int j, int buf) {
        const char* src = (const char*)g_x16 + (size_t)idxs[j] * 256;
        const uint32_t dst = sb + OFF_A + (uint32_t)buf * 32768u;
        #pragma unroll
        for (int c = 0; c < 4; ++c) {
            const int chunk = c0 + c;
            CP_ASYNC16(dst + tile_off(r, chunk * 8), src + chunk * 16);
        }
    };

    stage_A(0, 0);
    CP_COMMIT();       // group: A0

    // warp tiling: 4 (M) x 4 (N); warp tile = 32 rows x 32 cols
    const int wm = wid >> 2;
    const int wn = wid & 3;

    float acc[2][4][4];
    #pragma unroll
    for (int mt = 0; mt < 2; ++mt)
        #pragma unroll
        for (int nt = 0; nt < 4; ++nt)
            #pragma unroll
            for (int q = 0; q < 4; ++q) acc[mt][nt][q] = 0.0f;

    const int a_row  = (lid & 15);
    const int a_gsel = (lid >> 4);
    const int b_row  = (lid & 7);
    const int b_gsel = ((lid >> 3) & 1);

    #pragma unroll
    for (int j = 0; j < NSLOT; ++j) {
        if (j < NSLOT - 1) {
            stage_A(j + 1, (j + 1) & 1);
            CP_COMMIT();
            asm volatile("cp.async.wait_group 1;" ::: "memory");
        } else {
            asm volatile("cp.async.wait_group 0;" ::: "memory");
        }
        __syncthreads();   // W + A[j] visible to all warps

        const uint32_t wbase = sb + OFF_W + (uint32_t)j * 32768u;
        const uint32_t abase = sb + OFF_A + (uint32_t)(j & 1) * 32768u;
        #pragma unroll
        for (int kc = 0; kc < 8; ++kc) {
            uint32_t bh[4][2];
            const int gB = kc * 2 + b_gsel;
            #pragma unroll
            for (int nt = 0; nt < 4; ++nt) {
                const int nr = wn * 32 + nt * 8 + b_row;
                const uint32_t off =
                    (uint32_t)nr * 256u + (((uint32_t)(gB ^ (nr & 7))) << 4);
                ldsm_x2(bh[nt], wbase + off);
            }
            const int gA = kc * 2 + a_gsel;
            #pragma unroll
            for (int mt = 0; mt < 2; ++mt) {
                const int ar = wm * 32 + mt * 16 + a_row;
                const uint32_t off =
                    (uint32_t)ar * 256u + (((uint32_t)(gA ^ (ar & 7))) << 4);
                uint32_t ah[4];
                ldsm_x4(ah, abase + off);
                #pragma unroll
                for (int nt = 0; nt < 4; ++nt)
                    mma16816(acc[mt][nt], ah, bh[nt]);
            }
        }
        if (j < NSLOT - 1) __syncthreads();   // reads done before overwrite
    }

    // ---- epilogue --------------------------------------------------------------
    {
        const float* bs = (const float*)(smem + OFF_BIAS);
        const int rl = lid >> 2;
        const int cl = (lid & 3) * 2;
        #pragma unroll
        for (int mt = 0; mt < 2; ++mt) {
            const int r_base = row0 + wm * 32 + mt * 16 + rl;
            #pragma unroll
            for (int nt = 0; nt < 4; ++nt) {
                const int col = wn * 32 + nt * 8 + cl;
                const float b0 = bs[col], b1 = bs[col + 1];
                if (r_base < N) {
                    float2 vv = make_float2(acc[mt][nt][0] + b0,
                                            acc[mt][nt][1] + b1);
                    *(float2*)(out + (size_t)r_base * 128 + col) = vv;
                }
                if (r_base + 8 < N) {
                    float2 vv = make_float2(acc[mt][nt][2] + b0,
                                            acc[mt][nt][3] + b1);
                    *(float2*)(out + (size_t)(r_base + 8) * 128 + col) = vv;
                }
            }
        }
    }
}

// ---- launch ------------------------------------------------------------------
extern "C" void kernel_launch(void* const* d_in, const int* in_sizes, int n_in,
                              void* d_out, int out_size) {
    const float* x   = (const float*)d_in[0];
    const void*  nbr = d_in[1];
    const float* W   = (const float*)d_in[2];
    const float* b   = (const float*)d_in[3];
    float* out = (float*)d_out;
    const int N = in_sizes[0] / 128;
    const int tiles = (N + 127) / 128;
    const int ngroups = N * 16;   // 8 fp32 elems per group

    cudaFuncSetAttribute(mcconv_kernel,
                         cudaFuncAttributeMaxDynamicSharedMemorySize, SMEM_BYTES);

    prep_w_kernel<<<(NSLOT * 128 * 64 + 255) / 256, 256>>>(W);
    cvt_x_kernel<<<(ngroups + 255) / 256, 256>>>(x, ngroups);
    detect_kernel<<<1, 32>>>((const int*)nbr);
    mcconv_kernel<<<tiles, 512, SMEM_BYTES>>>(nbr, b, out, N);
}

// round 5
// speedup vs baseline: 2.9234x; 1.0021x over previous
#include <cuda_runtime.h>
#include <cuda_fp16.h>
#include <cstdint>

// ============================================================================
// MotherCubeConv: y[n] = concat(x[n], x[nbr0..3(n)]) @ W^T + b
//   N=200000, F_in=128, fan_in=640, F_out=128.
// fp16 mma.sync. R5: register-pipelined fragments (preload kc+1 during kc
// MMAs), B frags via ldmatrix.x4, fused prologue. W SMEM-resident, gathered
// A staged by cp.async into swizzled SMEM from a prebuilt fp16 image of x.
// ============================================================================

#define NSLOT 5
#define MAX_ROWS 200704

// ---- scratch (__device__ globals; no allocation allowed) -------------------
__device__ uint4 g_Wh[NSLOT * 2048];            // 5 x [128x128] fp16, swizzled
__device__ uint4 g_x16[(size_t)MAX_ROWS * 16];  // fp16 image of x (51.4MB)
__device__ int   g_is64;

// ---- helpers ----------------------------------------------------------------
__device__ __forceinline__ uint32_t smem_u32(const void* p) {
    uint32_t a;
    asm("{ .reg .u64 t; cvta.to.shared.u64 t, %1; cvt.u32.u64 %0, t; }"
        : "=r"(a) : "l"(p));
    return a;
}

__device__ __forceinline__ void ldsm_x4(uint32_t* r, uint32_t addr) {
    asm volatile("ldmatrix.sync.aligned.m8n8.x4.shared.b16 {%0,%1,%2,%3}, [%4];"
                 : "=r"(r[0]), "=r"(r[1]), "=r"(r[2]), "=r"(r[3]) : "r"(addr));
}

__device__ __forceinline__ void mma16816(float* d, const uint32_t* a,
                                         const uint32_t* b) {
    asm volatile(
        "mma.sync.aligned.m16n8k16.row.col.f32.f16.f16.f32 "
        "{%0,%1,%2,%3}, {%4,%5,%6,%7}, {%8,%9}, {%0,%1,%2,%3};"
        : "+f"(d[0]), "+f"(d[1]), "+f"(d[2]), "+f"(d[3])
        : "r"(a[0]), "r"(a[1]), "r"(a[2]), "r"(a[3]), "r"(b[0]), "r"(b[1]));
}

#define CP_ASYNC16(dst, src) \
    asm volatile("cp.async.cg.shared.global [%0], [%1], 16;" \
                 :: "r"(dst), "l"(src) : "memory")
#define CP_COMMIT() asm volatile("cp.async.commit_group;" ::: "memory")

// Swizzled byte offset inside one [128 rows x 128 fp16] tile (32KB).
__device__ __host__ __forceinline__ uint32_t tile_off(int row, int k) {
    uint32_t g = (uint32_t)(k >> 3);
    return (uint32_t)row * 256u + (((g ^ (uint32_t)(row & 7)) << 4)) +
           (uint32_t)(k & 7) * 2u;
}

// ---- fused prologue: cvt x -> fp16 image, W -> fp16 swizzled, dtype detect --
__global__ void prep_kernel(const float* __restrict__ x,
                            const float* __restrict__ W,
                            const int* __restrict__ nbr, int ngroups) {
    const int t = blockIdx.x * blockDim.x + threadIdx.x;
    if (t < ngroups) {
        const float4* s = (const float4*)x + (size_t)t * 2;
        float4 a = s[0], b = s[1];
        __half2 h0 = __floats2half2_rn(a.x, a.y);
        __half2 h1 = __floats2half2_rn(a.z, a.w);
        __half2 h2 = __floats2half2_rn(b.x, b.y);
        __half2 h3 = __floats2half2_rn(b.z, b.w);
        uint4 u;
        u.x = *(uint32_t*)&h0; u.y = *(uint32_t*)&h1;
        u.z = *(uint32_t*)&h2; u.w = *(uint32_t*)&h3;
        g_x16[t] = u;
    }
    if (t < NSLOT * 128 * 64) {
        int cp = t & 63;
        int f  = (t >> 6) & 127;
        int j  = t >> 13;
        int k  = cp * 2;
        __half2 h = __floats2half2_rn(W[f * 640 + j * 128 + k],
                                      W[f * 640 + j * 128 + k + 1]);
        *(uint32_t*)((char*)g_Wh + (size_t)j * 32768 + tile_off(f, k)) =
            *(uint32_t*)&h;
    }
    if (t == 0) {
        int all0 = 1;
        for (int i = 0; i < 64; i++)
            if (nbr[2 * i + 1] != 0) { all0 = 0; break; }
        g_is64 = all0;
    }
}

// ---- SMEM layout --------------------------------------------------------------
static constexpr uint32_t OFF_BIAS = 0;        // 512B
static constexpr uint32_t OFF_W    = 1024;     // 5 x 32KB
static constexpr uint32_t OFF_A    = 164864;   // 2 x 32KB
static constexpr uint32_t SMEM_BYTES = 230400;

__global__ void __launch_bounds__(512, 1)
mcconv_kernel(const void* __restrict__ nbr_raw,
              const float* __restrict__ bias_g, float* __restrict__ out, int N) {
    extern __shared__ char smem[];
    const uint32_t sb = smem_u32(smem);
    const int tid = threadIdx.x;
    const int wid = tid >> 5;
    const int lid = tid & 31;

    if (tid < 128) ((float*)(smem + OFF_BIAS))[tid] = bias_g[tid];

    // ---- stage all W (160KB) in one commit group ------------------------------
    {
        const char* src = (const char*)g_Wh;
        const uint32_t dst = sb + OFF_W;
        #pragma unroll
        for (int w = 0; w < 20; ++w) {
            const uint32_t e = (uint32_t)(tid + w * 512) * 16u;
            CP_ASYNC16(dst + e, src + e);
        }
        CP_COMMIT();   // group: W
    }

    // ---- per-thread gather assignment: 4 threads per row ----------------------
    const int row0 = blockIdx.x * 128;
    const int r    = tid >> 2;            // tile row 0..127
    const int c0   = (tid & 3) * 4;       // first of 4 16B-chunks (of 16)
    const int grow = row0 + r;
    const bool gvalid = grow < N;
    int idxs[NSLOT];
    idxs[0] = gvalid ? grow : 0;
    if (g_is64) {
        const long long* p = (const long long*)nbr_raw + (size_t)idxs[0] * 4;
        #pragma unroll
        for (int k = 0; k < 4; ++k) idxs[k + 1] = gvalid ? (int)p[k] : 0;
    } else {
        const int* p = (const int*)nbr_raw + (size_t)idxs[0] * 4;
        #pragma unroll
        for (int k = 0; k < 4; ++k) idxs[k + 1] = gvalid ? p[k] : 0;
    }

    auto stage_A = [&](int j, int buf) {
        const char* src = (const char*)g_x16 + (size_t)idxs[j] * 256;
        const uint32_t dst = sb + OFF_A + (uint32_t)buf * 32768u;
        #pragma unroll
        for (int c = 0; c < 4; ++c) {
            const int chunk = c0 + c;
            CP_ASYNC16(dst + tile_off(r, chunk * 8), src + chunk * 16);
        }
    };

    stage_A(0, 0);
    CP_COMMIT();       // group: A0

    // warp tiling: 4 (M) x 4 (N); warp tile = 32 rows x 32 cols
    const int wm = wid >> 2;
    const int wn = wid & 3;

    float acc[2][4][4];
    #pragma unroll
    for (int mt = 0; mt < 2; ++mt)
        #pragma unroll
        for (int nt = 0; nt < 4; ++nt)
            #pragma unroll
            for (int q = 0; q < 4; ++q) acc[mt][nt][q] = 0.0f;

    // per-lane ldmatrix addressing
    //   A x4: lanes 0-15 rows (lid&15), lanes 16-31 same rows, next k-group
    const int a_row  = (lid & 15);
    const int a_gsel = (lid >> 4);
    //   B x4: q = lid>>3: (nt_in_pair = q>>1, k-group = q&1), rows lid&7
    const int b_row  = (lid & 7);
    const int b_ntin = (lid >> 4);        // 0,1: which nt within the pair
    const int b_gsel = ((lid >> 3) & 1);  // k-group select

    #pragma unroll
    for (int j = 0; j < NSLOT; ++j) {
        if (j < NSLOT - 1) {
            stage_A(j + 1, (j + 1) & 1);
            CP_COMMIT();
            asm volatile("cp.async.wait_group 1;" ::: "memory");
        } else {
            asm volatile("cp.async.wait_group 0;" ::: "memory");
        }
        __syncthreads();   // W + A[j] visible to all warps

        const uint32_t wbase = sb + OFF_W + (uint32_t)j * 32768u;
        const uint32_t abase = sb + OFF_A + (uint32_t)(j & 1) * 32768u;

        // fragment pipeline: load kc frags into [kc&1], consume while loading kc+1
        uint32_t ah[2][2][4];   // [pipe][mt][reg]
        uint32_t bh[2][4][2];   // [pipe][nt][reg]

        auto load_frags = [&](int kc, int pipe) {
            // B: two x4 loads cover nt pairs {0,1} and {2,3}
            #pragma unroll
            for (int p = 0; p < 2; ++p) {
                const int nr = wn * 32 + p * 16 + b_ntin * 8 + b_row;
                const int g  = kc * 2 + b_gsel;
                const uint32_t off =
                    (uint32_t)nr * 256u + (((uint32_t)(g ^ (nr & 7))) << 4);
                uint32_t rr[4];
                ldsm_x4(rr, wbase + off);
                bh[pipe][p * 2 + 0][0] = rr[0];
                bh[pipe][p * 2 + 0][1] = rr[1];
                bh[pipe][p * 2 + 1][0] = rr[2];
                bh[pipe][p * 2 + 1][1] = rr[3];
            }
            // A: one x4 per mt
            const int gA = kc * 2 + a_gsel;
            #pragma unroll
            for (int mt = 0; mt < 2; ++mt) {
                const int ar = wm * 32 + mt * 16 + a_row;
                const uint32_t off =
                    (uint32_t)ar * 256u + (((uint32_t)(gA ^ (ar & 7))) << 4);
                ldsm_x4(ah[pipe][mt], abase + off);
            }
        };

        load_frags(0, 0);
        #pragma unroll
        for (int kc = 0; kc < 8; ++kc) {
            const int cur = kc & 1;
            if (kc < 7) load_frags(kc + 1, cur ^ 1);
            #pragma unroll
            for (int mt = 0; mt < 2; ++mt)
                #pragma unroll
                for (int nt = 0; nt < 4; ++nt)
                    mma16816(acc[mt][nt], ah[cur][mt], bh[cur][nt]);
        }
        if (j < NSLOT - 1) __syncthreads();   // reads done before overwrite
    }

    // ---- epilogue --------------------------------------------------------------
    {
        const float* bs = (const float*)(smem + OFF_BIAS);
        const int rl = lid >> 2;
        const int cl = (lid & 3) * 2;
        #pragma unroll
        for (int mt = 0; mt < 2; ++mt) {
            const int r_base = row0 + wm * 32 + mt * 16 + rl;
            #pragma unroll
            for (int nt = 0; nt < 4; ++nt) {
                const int col = wn * 32 + nt * 8 + cl;
                const float b0 = bs[col], b1 = bs[col + 1];
                if (r_base < N) {
                    float2 vv = make_float2(acc[mt][nt][0] + b0,
                                            acc[mt][nt][1] + b1);
                    *(float2*)(out + (size_t)r_base * 128 + col) = vv;
                }
                if (r_base + 8 < N) {
                    float2 vv = make_float2(acc[mt][nt][2] + b0,
                                            acc[mt][nt][3] + b1);
                    *(float2*)(out + (size_t)(r_base + 8) * 128 + col) = vv;
                }
            }
        }
    }
}

// ---- launch ------------------------------------------------------------------
extern "C" void kernel_launch(void* const* d_in, const int* in_sizes, int n_in,
                              void* d_out, int out_size) {
    const float* x   = (const float*)d_in[0];
    const void*  nbr = d_in[1];
    const float* W   = (const float*)d_in[2];
    const float* b   = (const float*)d_in[3];
    float* out = (float*)d_out;
    const int N = in_sizes[0] / 128;
    const int tiles = (N + 127) / 128;
    const int ngroups = N * 16;   // 8 fp32 elems per group

    cudaFuncSetAttribute(mcconv_kernel,
                         cudaFuncAttributeMaxDynamicSharedMemorySize, SMEM_BYTES);

    prep_kernel<<<(ngroups + 255) / 256, 256>>>(x, W, (const int*)nbr, ngroups);
    mcconv_kernel<<<tiles, 512, SMEM_BYTES>>>(nbr, b, out, N);
}